// round 16
// baseline (speedup 1.0000x reference)
#include <cuda_runtime.h>
#include <cuda.h>
#include <cstdint>

// EMA along T, round 15: TMA-fed smem pipeline at amp=1.125x.
// x: [B=8, T=4096, F=1024] fp32, y_t = 0.9*y_{t-1} + 0.1*x_t, y_{-1}=0.
//
// R12/R13 proved SPAN=512 (amp 1.125x) starves at 7 warps/SM because
// LDG-demand is warp-count-limited (4.9TB/s). TMA decouples outstanding
// bytes from warps: thread-0-issued bulk copies into a 4-stage smem ring
// keep ~12MB chip-wide in flight at any occupancy. This is the only
// mechanism that can combine amp=1.125x with the ~6TB/s wall.
// Fallback: if the tensormap entry point is unavailable, launch the banked
// champion (CHUNK=256/LOOKBACK=64 LDG kernel, 47.6us).

#define T_DIM    4096
#define F_DIM    1024
#define B_DIM    8
#define ALPHA    0.9f
#define OMALPHA  0.1f
#define F2 (F_DIM / 2)

// ---- TMA pipeline config ----
#define SPAN      512
#define LOOKBACK  64
#define ROWS      16                 // timesteps per TMA stage
#define LANES     64                 // float2 lanes per block (= threads)
#define ROW_BYTES (LANES * 8)        // 512 B
#define STAGE_BYTES (ROWS * ROW_BYTES) // 8 KB
#define STAGES    4
#define NSPAN     (T_DIM / SPAN)     // 8
#define WARM_ITERS (LOOKBACK / ROWS) // 4
#define OUT_ITERS  (SPAN / ROWS)     // 32

__device__ __forceinline__ void stcs2(float2* p, float2 v) {
    asm volatile("st.global.cs.v2.f32 [%0], {%1,%2};"
                 :: "l"(p), "f"(v.x), "f"(v.y) : "memory");
}

__device__ __forceinline__ uint32_t s2u(const void* p) {
    return (uint32_t)__cvta_generic_to_shared(p);
}

__device__ __forceinline__ void mbar_init(uint32_t a, uint32_t cnt) {
    asm volatile("mbarrier.init.shared.b64 [%0], %1;" :: "r"(a), "r"(cnt) : "memory");
}
__device__ __forceinline__ void mbar_expect_tx(uint32_t a, uint32_t bytes) {
    asm volatile("mbarrier.arrive.expect_tx.shared.b64 _, [%0], %1;"
                 :: "r"(a), "r"(bytes) : "memory");
}
__device__ __forceinline__ void mbar_wait(uint32_t a, uint32_t phase) {
    asm volatile(
        "{\n\t.reg .pred P;\n\t"
        "WL_%=:\n\t"
        "mbarrier.try_wait.parity.acquire.cta.shared::cta.b64 P, [%0], %1, 0x989680;\n\t"
        "@P bra WD_%=;\n\t"
        "bra WL_%=;\n\t"
        "WD_%=:\n\t}"
        :: "r"(a), "r"(phase) : "memory");
}
__device__ __forceinline__ void tma2d(uint32_t dst, const CUtensorMap* tm,
                                      int cx, int cy, uint32_t mbar) {
    asm volatile(
        "cp.async.bulk.tensor.2d.shared::cta.global.tile.mbarrier::complete_tx::bytes "
        "[%0], [%1, {%2, %3}], [%4];"
        :: "r"(dst), "l"(tm), "r"(cx), "r"(cy), "r"(mbar) : "memory");
}

__global__ __launch_bounds__(LANES, 4)
void ema_tma_kernel(const __grid_constant__ CUtensorMap tmap,
                    float* __restrict__ y) {
    __shared__ __align__(1024) unsigned char sbuf[STAGES * STAGE_BYTES];
    __shared__ __align__(8) unsigned long long mbar[STAGES];

    const int span = blockIdx.x;              // 0..7
    const int lg   = blockIdx.y;              // 0..7 lane group
    const int b    = blockIdx.z;              // 0..7
    const int tid  = threadIdx.x;             // 0..63

    const int t0 = span * SPAN;
    const int tw = (span > 0) ? (t0 - LOOKBACK) : 0;
    const int warm = (span > 0) ? WARM_ITERS : 0;
    const int total = warm + OUT_ITERS;
    const int rowbase = b * T_DIM + tw;       // global row of iter 0
    const int cx = lg * (LANES * 2);          // element coord in F

    const uint32_t mb0 = s2u(&mbar[0]);
    const uint32_t sb0 = s2u(&sbuf[0]);

    if (tid == 0) {
        #pragma unroll
        for (int s = 0; s < STAGES; ++s) mbar_init(mb0 + 8u * s, 1);
    }
    __syncthreads();

    // prologue: fill the ring
    if (tid == 0) {
        #pragma unroll
        for (int s = 0; s < STAGES; ++s) {
            if (s < total) {
                mbar_expect_tx(mb0 + 8u * s, STAGE_BYTES);
                tma2d(sb0 + s * STAGE_BYTES, &tmap, cx, rowbase + s * ROWS,
                      mb0 + 8u * s);
            }
        }
    }

    float ax = 0.f, ay = 0.f;
    const int f2g = lg * LANES + tid;
    float2* __restrict__ yp =
        reinterpret_cast<float2*>(y) + (size_t)b * T_DIM * F2 + f2g;

    for (int i = 0; i < total; ++i) {
        const int si = i & (STAGES - 1);
        const uint32_t ph = (uint32_t)((i / STAGES) & 1);
        mbar_wait(mb0 + 8u * si, ph);

        const float2* row0 =
            reinterpret_cast<const float2*>(sbuf + si * STAGE_BYTES) + tid;
        const int tcur = tw + i * ROWS;

        if (tcur >= t0) {
            // output iterations (uniform per iter: warm is a multiple of ROWS)
            #pragma unroll
            for (int r = 0; r < ROWS; ++r) {
                float2 v = row0[r * LANES];
                ax = fmaf(ALPHA, ax, OMALPHA * v.x);
                ay = fmaf(ALPHA, ay, OMALPHA * v.y);
                float2 o; o.x = ax; o.y = ay;
                stcs2(&yp[(size_t)(tcur + r) * F2], o);
            }
        } else {
            // warmup iterations: FMA only
            #pragma unroll
            for (int r = 0; r < ROWS; ++r) {
                float2 v = row0[r * LANES];
                ax = fmaf(ALPHA, ax, OMALPHA * v.x);
                ay = fmaf(ALPHA, ay, OMALPHA * v.y);
            }
        }

        __syncthreads();   // all lanes done with stage si before refill
        const int ni = i + STAGES;
        if (tid == 0 && ni < total) {
            mbar_expect_tx(mb0 + 8u * si, STAGE_BYTES);
            tma2d(sb0 + si * STAGE_BYTES, &tmap, cx, rowbase + ni * ROWS,
                  mb0 + 8u * si);
        }
    }
}

// ---------- fallback: banked champion (CHUNK=256/LOOKBACK=64, LDG) ----------
#define CHUNK    256
#define NCHUNK   (T_DIM / CHUNK)

__global__ __launch_bounds__(128, 8)
void ema_chunk_kernel(const float* __restrict__ x, float* __restrict__ y) {
    const int chunk = blockIdx.x;
    const int f2 = blockIdx.y * blockDim.x + threadIdx.x;
    const int b = blockIdx.z;

    const int t0 = chunk * CHUNK;
    const int tw = (t0 >= LOOKBACK) ? (t0 - LOOKBACK) : 0;

    const float2* __restrict__ xp =
        reinterpret_cast<const float2*>(x) + (size_t)b * T_DIM * F2 + f2;
    float2* __restrict__ yp =
        reinterpret_cast<float2*>(y) + (size_t)b * T_DIM * F2 + f2;

    float ax = 0.f, ay = 0.f;
    #pragma unroll 16
    for (int t = tw; t < t0; ++t) {
        float2 v = __ldg(&xp[(size_t)t * F2]);
        ax = fmaf(ALPHA, ax, OMALPHA * v.x);
        ay = fmaf(ALPHA, ay, OMALPHA * v.y);
    }
    #pragma unroll 16
    for (int i = 0; i < CHUNK; ++i) {
        const int tt = t0 + i;
        float2 v = __ldg(&xp[(size_t)tt * F2]);
        ax = fmaf(ALPHA, ax, OMALPHA * v.x);
        ay = fmaf(ALPHA, ay, OMALPHA * v.y);
        float2 o; o.x = ax; o.y = ay;
        stcs2(&yp[(size_t)tt * F2], o);
    }
}

// ---------- host ----------
typedef CUresult (*PFN_encode)(CUtensorMap*, CUtensorMapDataType, cuuint32_t,
                               void*, const cuuint64_t*, const cuuint64_t*,
                               const cuuint32_t*, const cuuint32_t*,
                               CUtensorMapInterleave, CUtensorMapSwizzle,
                               CUtensorMapL2promotion, CUtensorMapFloatOOBfill);

extern "C" void kernel_launch(void* const* d_in, const int* in_sizes, int n_in,
                              void* d_out, int out_size) {
    (void)in_sizes; (void)n_in; (void)out_size;
    const float* x = (const float*)d_in[0];
    float* y = (float*)d_out;

    PFN_encode enc = nullptr;
    cudaDriverEntryPointQueryResult qr = cudaDriverEntryPointSymbolNotFound;
    cudaError_t e = cudaGetDriverEntryPointByVersion(
        "cuTensorMapEncodeTiled", (void**)&enc, 12000, cudaEnableDefault, &qr);

    bool tma_ok = (e == cudaSuccess) && (qr == cudaDriverEntryPointSuccess) && enc;

    if (tma_ok) {
        CUtensorMap tmap;
        cuuint64_t dims[2]    = {(cuuint64_t)F_DIM, (cuuint64_t)B_DIM * T_DIM};
        cuuint64_t strides[1] = {(cuuint64_t)F_DIM * sizeof(float)};
        cuuint32_t box[2]     = {LANES * 2, ROWS};   // 128 floats x 16 rows
        cuuint32_t estr[2]    = {1, 1};
        CUresult r = enc(&tmap, CU_TENSOR_MAP_DATA_TYPE_FLOAT32, 2, (void*)x,
                         dims, strides, box, estr,
                         CU_TENSOR_MAP_INTERLEAVE_NONE,
                         CU_TENSOR_MAP_SWIZZLE_NONE,
                         CU_TENSOR_MAP_L2_PROMOTION_L2_128B,
                         CU_TENSOR_MAP_FLOAT_OOB_FILL_NONE);
        if (r == CUDA_SUCCESS) {
            dim3 block(LANES, 1, 1);
            dim3 grid(NSPAN, F2 / LANES, B_DIM);   // (8, 8, 8) = 512 blocks
            ema_tma_kernel<<<grid, block>>>(tmap, y);
            return;
        }
    }

    // fallback: champion
    dim3 block(128, 1, 1);
    dim3 grid(NCHUNK, F2 / 128, B_DIM);
    ema_chunk_kernel<<<grid, block>>>(x, y);
}